// round 15
// baseline (speedup 1.0000x reference)
#include <cuda_runtime.h>
#include <cuda_fp16.h>
#include <math.h>
#include <stdint.h>

// ---------------- problem dims ----------------
#define BB 2
#define LL 4096
#define DD 1024
#define NN 16
#define KK 4
#define SEG 128
#define TSEG 32
#define MROWS (BB*LL)       // 8192
#define Y_ELEMS (BB*LL*DD)  // 8388608

// ---------------- scratch ----------------
__device__ float g_xssm[Y_ELEMS];                  // fp32 x_ssm
__device__ __align__(16) __half g_gh[Y_ELEMS];     // fp16 silu(gate)
__device__ __align__(16) __half g_xch[Y_ELEMS];    // fp16 x_conv
__device__ __align__(16) __half g_xh[Y_ELEMS];     // fp16 x
__device__ __align__(16) __half g_ygh[Y_ELEMS];    // fp16 y*silu(gate)
__device__ __align__(16) uint32_t g_wp1[(DD/2)*(2*DD)];  // W_in pair-packed
__device__ __align__(16) uint32_t g_wp2[(DD/2)*DD];      // W_out pair-packed
__device__ __align__(16) uint32_t g_wxh[(DD/2)*32];      // W_x pair-packed fp16
__device__ __align__(16) float g_adn[DD*NN];       // exp(-exp(A_log))
__device__ __align__(16) float g_adp[DD*NN];       // Adn^TSEG
__device__ float g_B[BB*LL*NN];
__device__ float g_C[BB*LL*NN];
__device__ float g_hseg[BB*SEG*NN*DD];
__device__ float g_h0[BB*SEG*NN*DD];

__device__ __forceinline__ uint32_t h2u(__half2 h) {
    union { __half2 h; uint32_t u; } cvt; cvt.h = h; return cvt.u;
}
__device__ __forceinline__ __half2 u2h(uint32_t u) {
    union { uint32_t u; __half2 h; } cvt; cvt.u = u; return cvt.h;
}

// ---------------- merged prep ----------------
#define X4    (Y_ELEMS/4)
#define WP1N  ((DD/2)*(2*DD))
#define WP2N  ((DD/2)*DD)
#define WXHN  ((DD/2)*32)
#define ADNN  (DD*NN)
#define PREP_TOTAL (X4 + WP1N + WP2N + WXHN + ADNN)

__global__ void prep_kernel(const float* __restrict__ x,
                            const float* __restrict__ W_in,
                            const float* __restrict__ W_out,
                            const float* __restrict__ W_x,
                            const float* __restrict__ A_log,
                            float* __restrict__ tail)
{
    int i = blockIdx.x * blockDim.x + threadIdx.x;
    if (blockIdx.x == 0 && threadIdx.x < BB * NN) tail[threadIdx.x] = 0.0f;
    if (i >= PREP_TOTAL) return;
    if (i < X4) {
        float4 v = ((const float4*)x)[i];
        uint2 o;
        o.x = h2u(__floats2half2_rn(v.x, v.y));
        o.y = h2u(__floats2half2_rn(v.z, v.w));
        ((uint2*)g_xh)[i] = o;
    } else if (i < X4 + WP1N) {
        int j = i - X4;
        int k2 = j >> 11, n = j & 2047;
        float lo = W_in[(size_t)(2 * k2) * 2048 + n];
        float hi = W_in[(size_t)(2 * k2 + 1) * 2048 + n];
        g_wp1[j] = h2u(__floats2half2_rn(lo, hi));
    } else if (i < X4 + WP1N + WP2N) {
        int j = i - X4 - WP1N;
        int k2 = j >> 10, n = j & 1023;
        float lo = W_out[(size_t)(2 * k2) * 1024 + n];
        float hi = W_out[(size_t)(2 * k2 + 1) * 1024 + n];
        g_wp2[j] = h2u(__floats2half2_rn(lo, hi));
    } else if (i < X4 + WP1N + WP2N + WXHN) {
        int j = i - X4 - WP1N - WP2N;
        int k2 = j >> 5, n = j & 31;
        float lo = W_x[(size_t)(2 * k2) * 32 + n];
        float hi = W_x[(size_t)(2 * k2 + 1) * 32 + n];
        g_wxh[j] = h2u(__floats2half2_rn(lo, hi));
    } else {
        int j = i - X4 - WP1N - WP2N - WXHN;
        float a = expf(-expf(A_log[j]));
        g_adn[j] = a;
        float p = a;
        #pragma unroll
        for (int q = 0; q < 5; q++) p = p * p;   // a^32 = a^TSEG
        g_adp[j] = p;
    }
}

// ======= fp16 mma.sync GEMM (m16n8k16): 128x128 block, 64x32 warp ======
#define GBM 128
#define GBN 128
#define GBK 32
#define AWSTRIDE 20
#define BWSTRIDE 136
#define A_STGW (GBM*AWSTRIDE)
#define B_STGW (16*BWSTRIDE)
#define STAGES 3
#define GEMM_SMEM (STAGES*(A_STGW+B_STGW)*4)   // 56832 bytes

__device__ __forceinline__ void cpasync16(void* dst, const void* src) {
    uint32_t s = (uint32_t)__cvta_generic_to_shared(dst);
    asm volatile("cp.async.cg.shared.global [%0], [%1], 16;\n" :: "r"(s), "l"(src));
}

// mode 0: plain fp32 C0. mode 1: cols<halfN -> C0 fp32, cols>=halfN -> silu fp16 C1h
__global__ __launch_bounds__(256)
void hgemm_kernel(const __half* __restrict__ A, const uint32_t* __restrict__ Bp,
                  const float* __restrict__ bias,
                  float* __restrict__ C0, __half* __restrict__ C1h,
                  int M, int N, int K, int mode)
{
    extern __shared__ uint32_t smw[];
    uint32_t* As_ = smw;
    uint32_t* Bs_ = smw + STAGES * A_STGW;

    const int tid  = threadIdx.x;
    const int lane = tid & 31;
    const int wid  = tid >> 5;
    const int wm   = wid >> 2;
    const int wn   = wid & 3;
    const int row_c = blockIdx.y * GBM;
    const int col_c = blockIdx.x * GBN;
    const int r  = lane >> 2;
    const int cq = lane & 3;

    float acc[4][4][4];
    #pragma unroll
    for (int i = 0; i < 4; i++)
        #pragma unroll
        for (int j = 0; j < 4; j++)
            #pragma unroll
            for (int v = 0; v < 4; v++) acc[i][j][v] = 0.0f;

    auto prefetch = [&](int k0, int st) {
        uint32_t* Asb = As_ + st * A_STGW;
        uint32_t* Bsb = Bs_ + st * B_STGW;
        #pragma unroll
        for (int s = 0; s < 2; s++) {
            int i2 = tid + s * 256;
            int arow = i2 >> 2, asub = i2 & 3;
            cpasync16(&Asb[arow * AWSTRIDE + asub * 4],
                      A + (size_t)(row_c + arow) * K + k0 + asub * 8);
            int brow = i2 >> 5, bsub = (i2 & 31) * 4;
            cpasync16(&Bsb[brow * BWSTRIDE + bsub],
                      Bp + (size_t)(k0 / 2 + brow) * N + col_c + bsub);
        }
        asm volatile("cp.async.commit_group;");
    };

    const int nchunks = K / GBK;   // 32
    prefetch(0, 0);
    prefetch(GBK, 1);

    for (int ch = 0; ch < nchunks; ch++) {
        if (ch >= nchunks - 2) asm volatile("cp.async.wait_group 0;");
        else                   asm volatile("cp.async.wait_group 1;");
        __syncthreads();
        if (ch + 2 < nchunks) prefetch((ch + 2) * GBK, (ch + 2) % STAGES);

        const uint32_t* Asb = As_ + (ch % STAGES) * A_STGW;
        const uint32_t* Bsb = Bs_ + (ch % STAGES) * B_STGW;

        #pragma unroll
        for (int ks = 0; ks < 2; ks++) {
            uint32_t af[4][4], bf[4][2];
            #pragma unroll
            for (int mi = 0; mi < 4; mi++) {
                int row = wm * 64 + mi * 16 + r;
                int w0  = ks * 8 + cq;
                af[mi][0] = Asb[row * AWSTRIDE + w0];
                af[mi][1] = Asb[(row + 8) * AWSTRIDE + w0];
                af[mi][2] = Asb[row * AWSTRIDE + w0 + 4];
                af[mi][3] = Asb[(row + 8) * AWSTRIDE + w0 + 4];
            }
            #pragma unroll
            for (int ni = 0; ni < 4; ni++) {
                int col = wn * 32 + ni * 8 + r;
                bf[ni][0] = Bsb[(ks * 8 + cq) * BWSTRIDE + col];
                bf[ni][1] = Bsb[(ks * 8 + cq + 4) * BWSTRIDE + col];
            }
            #pragma unroll
            for (int mi = 0; mi < 4; mi++)
                #pragma unroll
                for (int ni = 0; ni < 4; ni++) {
                    asm volatile(
                        "mma.sync.aligned.m16n8k16.row.col.f32.f16.f16.f32 "
                        "{%0,%1,%2,%3}, {%4,%5,%6,%7}, {%8,%9}, {%0,%1,%2,%3};"
                        : "+f"(acc[mi][ni][0]), "+f"(acc[mi][ni][1]),
                          "+f"(acc[mi][ni][2]), "+f"(acc[mi][ni][3])
                        : "r"(af[mi][0]), "r"(af[mi][1]),
                          "r"(af[mi][2]), "r"(af[mi][3]),
                          "r"(bf[ni][0]), "r"(bf[ni][1]));
                }
        }
        __syncthreads();
    }

    const int halfN = N >> 1;
    const bool gate_side = (mode == 1) && (col_c >= halfN);
    const int outw = (mode == 1) ? halfN : N;
    const int colsub = gate_side ? halfN : 0;

    #pragma unroll
    for (int mi = 0; mi < 4; mi++) {
        #pragma unroll
        for (int ni = 0; ni < 4; ni++) {
            int r0   = row_c + wm * 64 + mi * 16 + r;
            int colg = col_c + wn * 32 + ni * 8 + cq * 2;
            float b0 = bias[colg], b1 = bias[colg + 1];
            #pragma unroll
            for (int hv = 0; hv < 2; hv++) {
                int rr = r0 + hv * 8;
                float vx = acc[mi][ni][hv * 2 + 0] + b0;
                float vy = acc[mi][ni][hv * 2 + 1] + b1;
                if (gate_side) {
                    vx = vx / (1.0f + expf(-vx));
                    vy = vy / (1.0f + expf(-vy));
                    *(__half2*)(C1h + (size_t)rr * outw + colg - colsub) =
                        __floats2half2_rn(vx, vy);
                } else {
                    *(float2*)(C0 + (size_t)rr * outw + colg - colsub) =
                        make_float2(vx, vy);
                }
            }
        }
    }
}

// ------- depthwise causal conv (K=4) + SiLU, fp32 in / fp16 out --------
__global__ void conv_silu_kernel(const float* __restrict__ w,
                                 const float* __restrict__ cb)
{
    int idx = blockIdx.x * blockDim.x + threadIdx.x;
    if (idx >= Y_ELEMS / 16) return;
    int d0 = (idx & 255) * 4;
    int l0 = ((idx >> 8) & 1023) * 4;
    int b  = idx >> 18;
    const float* base = g_xssm + (size_t)b * LL * DD;

    float4 xv[7];
    #pragma unroll
    for (int j = 0; j < 7; j++) {
        int l = l0 - 3 + j;
        xv[j] = (l >= 0) ? *(const float4*)(base + (size_t)l * DD + d0)
                         : make_float4(0.f, 0.f, 0.f, 0.f);
    }
    float4 wr0 = *(const float4*)(w + (d0 + 0) * KK);
    float4 wr1 = *(const float4*)(w + (d0 + 1) * KK);
    float4 wr2 = *(const float4*)(w + (d0 + 2) * KK);
    float4 wr3 = *(const float4*)(w + (d0 + 3) * KK);
    float4 cbv = *(const float4*)(cb + d0);

    __half* outp = g_xch + (size_t)b * LL * DD;
    #pragma unroll
    for (int l = 0; l < 4; l++) {
        float4 v;
        v.x = cbv.x + wr0.x*xv[l].x + wr0.y*xv[l+1].x + wr0.z*xv[l+2].x + wr0.w*xv[l+3].x;
        v.y = cbv.y + wr1.x*xv[l].y + wr1.y*xv[l+1].y + wr1.z*xv[l+2].y + wr1.w*xv[l+3].y;
        v.z = cbv.z + wr2.x*xv[l].z + wr2.y*xv[l+1].z + wr2.z*xv[l+2].z + wr2.w*xv[l+3].z;
        v.w = cbv.w + wr3.x*xv[l].w + wr3.y*xv[l+1].w + wr3.z*xv[l+2].w + wr3.w*xv[l+3].w;
        v.x = v.x / (1.0f + expf(-v.x));
        v.y = v.y / (1.0f + expf(-v.y));
        v.z = v.z / (1.0f + expf(-v.z));
        v.w = v.w / (1.0f + expf(-v.w));
        uint2 o;
        o.x = h2u(__floats2half2_rn(v.x, v.y));
        o.y = h2u(__floats2half2_rn(v.z, v.w));
        *(uint2*)(outp + (size_t)(l0 + l) * DD + d0) = o;
    }
}

// --------- BC via fp16 tensor cores: 32 rows/block, 256 blocks ----------
#define BCA_STR 20      // uint32 per 32-half A row
#define BCW_STR 40      // uint32 per W pair-row

__global__ __launch_bounds__(64)
void bc_mma_kernel(const uint32_t* __restrict__ Wxh, const float* __restrict__ bx)
{
    __shared__ uint32_t As[3][32 * BCA_STR];
    __shared__ uint32_t Ws[3][16 * BCW_STR];

    const int tid  = threadIdx.x;        // 0..63
    const int lane = tid & 31;
    const int wid  = tid >> 5;           // 0..1
    const int r    = lane >> 2;
    const int cq   = lane & 3;
    const int r0   = blockIdx.x * 32;

    float acc[4][4];
    #pragma unroll
    for (int i = 0; i < 4; i++)
        #pragma unroll
        for (int v = 0; v < 4; v++) acc[i][v] = 0.0f;

    auto prefetch = [&](int ch, int st) {
        const int k0 = ch * 32;          // halves
        #pragma unroll
        for (int p = 0; p < 2; p++) {    // A: 32 rows x 4 pieces = 128
            int i2 = tid + p * 64;
            int row = i2 >> 2, sub = i2 & 3;
            cpasync16(&As[st][row * BCA_STR + sub * 4],
                      g_xch + (size_t)(r0 + row) * DD + k0 + sub * 8);
        }
        #pragma unroll
        for (int p = 0; p < 2; p++) {    // W: 16 pair-rows x 8 pieces = 128
            int i2 = tid + p * 64;
            int row = i2 >> 3, sub = i2 & 7;
            cpasync16(&Ws[st][row * BCW_STR + sub * 4],
                      Wxh + (size_t)(k0 / 2 + row) * 32 + sub * 4);
        }
        asm volatile("cp.async.commit_group;");
    };

    const int nch = DD / 32;   // 32
    prefetch(0, 0);
    prefetch(1, 1);

    for (int ch = 0; ch < nch; ch++) {
        if (ch >= nch - 2) asm volatile("cp.async.wait_group 0;");
        else               asm volatile("cp.async.wait_group 1;");
        __syncthreads();
        if (ch + 2 < nch) prefetch(ch + 2, (ch + 2) % 3);

        const uint32_t* Asb = As[ch % 3];
        const uint32_t* Wsb = Ws[ch % 3];
        #pragma unroll
        for (int ks = 0; ks < 2; ks++) {
            uint32_t af[4], bf[4][2];
            int row = wid * 16 + r;
            int w0  = ks * 8 + cq;
            af[0] = Asb[row * BCA_STR + w0];
            af[1] = Asb[(row + 8) * BCA_STR + w0];
            af[2] = Asb[row * BCA_STR + w0 + 4];
            af[3] = Asb[(row + 8) * BCA_STR + w0 + 4];
            #pragma unroll
            for (int ni = 0; ni < 4; ni++) {
                bf[ni][0] = Wsb[(ks * 8 + cq) * BCW_STR + ni * 8 + r];
                bf[ni][1] = Wsb[(ks * 8 + cq + 4) * BCW_STR + ni * 8 + r];
            }
            #pragma unroll
            for (int ni = 0; ni < 4; ni++) {
                asm volatile(
                    "mma.sync.aligned.m16n8k16.row.col.f32.f16.f16.f32 "
                    "{%0,%1,%2,%3}, {%4,%5,%6,%7}, {%8,%9}, {%0,%1,%2,%3};"
                    : "+f"(acc[ni][0]), "+f"(acc[ni][1]),
                      "+f"(acc[ni][2]), "+f"(acc[ni][3])
                    : "r"(af[0]), "r"(af[1]), "r"(af[2]), "r"(af[3]),
                      "r"(bf[ni][0]), "r"(bf[ni][1]));
            }
        }
        __syncthreads();
    }

    #pragma unroll
    for (int ni = 0; ni < 4; ni++) {
        #pragma unroll
        for (int v = 0; v < 4; v++) {
            int row = r0 + wid * 16 + r + (v >> 1) * 8;
            int col = ni * 8 + cq * 2 + (v & 1);
            float val = acc[ni][v] + bx[col];
            if (col < NN) g_B[row * NN + col] = val;
            else          g_C[row * NN + (col - NN)] = val;
        }
    }
}

// ---------------- scan pass 1 (TSEG=32, one chunk) ----------------
__global__ __launch_bounds__(256)
void scan1_kernel()
{
    __shared__ float Xsm[32][256];
    __shared__ __align__(16) float Bsm[32][16];

    const int tid = threadIdx.x;
    const int dt  = blockIdx.x & 3;
    const int s   = (blockIdx.x >> 2) & (SEG - 1);
    const int b   = blockIdx.x >> 9;
    const int d   = dt * 256 + tid;
    const int t0  = s * TSEG;

    float Adn[16];
    #pragma unroll
    for (int q = 0; q < 4; q++)
        *(float4*)&Adn[q * 4] = *(const float4*)&g_adn[d * NN + q * 4];

    float h[16];
    #pragma unroll
    for (int n = 0; n < 16; n++) h[n] = 0.0f;

    const float* Bp = g_B + (size_t)b * LL * NN;
    if (tid < 128)
        ((float4*)Bsm)[tid] = ((const float4*)(Bp + (size_t)t0 * NN))[tid];
    {
        const uint32_t* xu = (const uint32_t*)(g_xch + (size_t)b * LL * DD + dt * 256);
        #pragma unroll
        for (int p = 0; p < 16; p++) {
            int j = tid + p * 256;
            int row = j >> 7, c = j & 127;
            float2 f = __half22float2(u2h(xu[(size_t)(t0 + row) * (DD / 2) + c]));
            Xsm[row][c * 2]     = f.x;
            Xsm[row][c * 2 + 1] = f.y;
        }
    }
    __syncthreads();

    #pragma unroll 4
    for (int tl = 0; tl < 32; tl++) {
        float xc = Xsm[tl][tid];
        float4 b0 = *(const float4*)&Bsm[tl][0];
        float4 b1 = *(const float4*)&Bsm[tl][4];
        float4 b2 = *(const float4*)&Bsm[tl][8];
        float4 b3 = *(const float4*)&Bsm[tl][12];
        h[0]  = fmaf(Adn[0],  h[0],  xc * b0.x);
        h[1]  = fmaf(Adn[1],  h[1],  xc * b0.y);
        h[2]  = fmaf(Adn[2],  h[2],  xc * b0.z);
        h[3]  = fmaf(Adn[3],  h[3],  xc * b0.w);
        h[4]  = fmaf(Adn[4],  h[4],  xc * b1.x);
        h[5]  = fmaf(Adn[5],  h[5],  xc * b1.y);
        h[6]  = fmaf(Adn[6],  h[6],  xc * b1.z);
        h[7]  = fmaf(Adn[7],  h[7],  xc * b1.w);
        h[8]  = fmaf(Adn[8],  h[8],  xc * b2.x);
        h[9]  = fmaf(Adn[9],  h[9],  xc * b2.y);
        h[10] = fmaf(Adn[10], h[10], xc * b2.z);
        h[11] = fmaf(Adn[11], h[11], xc * b2.w);
        h[12] = fmaf(Adn[12], h[12], xc * b3.x);
        h[13] = fmaf(Adn[13], h[13], xc * b3.y);
        h[14] = fmaf(Adn[14], h[14], xc * b3.z);
        h[15] = fmaf(Adn[15], h[15], xc * b3.w);
    }
    #pragma unroll
    for (int n = 0; n < 16; n++)
        g_hseg[((size_t)(b * SEG + s) * NN + n) * DD + d] = h[n];
}

// ---------------- combine ----------------
__global__ __launch_bounds__(256)
void combine_kernel(float* __restrict__ fstate)
{
    int idx = blockIdx.x * 256 + threadIdx.x;
    int d = idx & (DD - 1);
    int bn = idx >> 10;
    int n = bn & 15;
    int b = bn >> 4;

    float p = g_adp[d * NN + n];

    size_t base = ((size_t)(b * SEG) * NN + n) * DD + d;
    const size_t stride = (size_t)NN * DD;
    float h = 0.0f;
    #pragma unroll 4
    for (int s = 0; s < SEG; s++) {
        g_h0[base + s * stride] = h;
        h = fmaf(p, h, g_hseg[base + s * stride]);
    }
    #pragma unroll
    for (int off = 16; off >= 1; off >>= 1)
        h += __shfl_xor_sync(0xffffffffu, h, off);
    if ((threadIdx.x & 31) == 0)
        atomicAdd(&fstate[b * NN + n], h * (1.0f / (float)DD));
}

// ---------------- scan pass 2 (TSEG=32, one chunk) ----------------
__global__ __launch_bounds__(256)
void scan2_kernel(const float* __restrict__ Dp)
{
    __shared__ float Xsm[32][256];
    __shared__ __align__(16) float Bsm[32][16];
    __shared__ __align__(16) float Csm[32][16];

    const int tid = threadIdx.x;
    const int dt  = blockIdx.x & 3;
    const int s   = (blockIdx.x >> 2) & (SEG - 1);
    const int b   = blockIdx.x >> 9;
    const int d   = dt * 256 + tid;
    const int t0  = s * TSEG;

    float Adn[16];
    #pragma unroll
    for (int q = 0; q < 4; q++)
        *(float4*)&Adn[q * 4] = *(const float4*)&g_adn[d * NN + q * 4];
    const float Dd = Dp[d];

    float h[16];
    {
        size_t base = ((size_t)(b * SEG + s) * NN) * DD + d;
        #pragma unroll
        for (int n = 0; n < 16; n++) h[n] = g_h0[base + (size_t)n * DD];
    }

    const float* Bp = g_B + (size_t)b * LL * NN;
    const float* Cp = g_C + (size_t)b * LL * NN;
    if (tid < 128) {
        ((float4*)Bsm)[tid] = ((const float4*)(Bp + (size_t)t0 * NN))[tid];
        ((float4*)Csm)[tid] = ((const float4*)(Cp + (size_t)t0 * NN))[tid];
    }
    {
        const uint32_t* xu = (const uint32_t*)(g_xch + (size_t)b * LL * DD + dt * 256);
        #pragma unroll
        for (int p = 0; p < 16; p++) {
            int j = tid + p * 256;
            int row = j >> 7, c = j & 127;
            float2 f = __half22float2(u2h(xu[(size_t)(t0 + row) * (DD / 2) + c]));
            Xsm[row][c * 2]     = f.x;
            Xsm[row][c * 2 + 1] = f.y;
        }
    }
    __syncthreads();

    const __half* gp = g_gh  + (size_t)b * LL * DD + dt * 256;
    __half*      yp  = g_ygh + (size_t)b * LL * DD + dt * 256;

    #pragma unroll 2
    for (int tl = 0; tl < 32; tl++) {
        float xc = Xsm[tl][tid];
        float4 b0 = *(const float4*)&Bsm[tl][0];
        float4 b1 = *(const float4*)&Bsm[tl][4];
        float4 b2 = *(const float4*)&Bsm[tl][8];
        float4 b3 = *(const float4*)&Bsm[tl][12];
        h[0]  = fmaf(Adn[0],  h[0],  xc * b0.x);
        h[1]  = fmaf(Adn[1],  h[1],  xc * b0.y);
        h[2]  = fmaf(Adn[2],  h[2],  xc * b0.z);
        h[3]  = fmaf(Adn[3],  h[3],  xc * b0.w);
        h[4]  = fmaf(Adn[4],  h[4],  xc * b1.x);
        h[5]  = fmaf(Adn[5],  h[5],  xc * b1.y);
        h[6]  = fmaf(Adn[6],  h[6],  xc * b1.z);
        h[7]  = fmaf(Adn[7],  h[7],  xc * b1.w);
        h[8]  = fmaf(Adn[8],  h[8],  xc * b2.x);
        h[9]  = fmaf(Adn[9],  h[9],  xc * b2.y);
        h[10] = fmaf(Adn[10], h[10], xc * b2.z);
        h[11] = fmaf(Adn[11], h[11], xc * b2.w);
        h[12] = fmaf(Adn[12], h[12], xc * b3.x);
        h[13] = fmaf(Adn[13], h[13], xc * b3.y);
        h[14] = fmaf(Adn[14], h[14], xc * b3.z);
        h[15] = fmaf(Adn[15], h[15], xc * b3.w);
        float4 c0 = *(const float4*)&Csm[tl][0];
        float4 c1 = *(const float4*)&Csm[tl][4];
        float4 c2 = *(const float4*)&Csm[tl][8];
        float4 c3 = *(const float4*)&Csm[tl][12];
        float y0 = fmaf(c0.x, h[0],  fmaf(c0.y, h[1],
                   fmaf(c0.z, h[2],  c0.w * h[3])));
        float y1 = fmaf(c1.x, h[4],  fmaf(c1.y, h[5],
                   fmaf(c1.z, h[6],  c1.w * h[7])));
        float y2 = fmaf(c2.x, h[8],  fmaf(c2.y, h[9],
                   fmaf(c2.z, h[10], c2.w * h[11])));
        float y3 = fmaf(c3.x, h[12], fmaf(c3.y, h[13],
                   fmaf(c3.z, h[14], c3.w * h[15])));
        float y = ((y0 + y1) + (y2 + y3)) + Dd * xc;
        float gv = __half2float(gp[(size_t)(t0 + tl) * DD + tid]);
        yp[(size_t)(t0 + tl) * DD + tid] = __float2half_rn(y * gv);
    }
}

// ---------------- launcher ----------------
extern "C" void kernel_launch(void* const* d_in, const int* in_sizes, int n_in,
                              void* d_out, int out_size)
{
    const float* x      = (const float*)d_in[0];
    const float* W_in   = (const float*)d_in[1];
    const float* b_in   = (const float*)d_in[2];
    const float* conv_w = (const float*)d_in[3];
    const float* conv_b = (const float*)d_in[4];
    const float* W_x    = (const float*)d_in[5];
    const float* b_x    = (const float*)d_in[6];
    const float* A_log  = (const float*)d_in[7];
    const float* D_par  = (const float*)d_in[8];
    const float* W_out  = (const float*)d_in[9];
    const float* b_out  = (const float*)d_in[10];
    float* out = (float*)d_out;

    static int attr_done = 0;
    if (!attr_done) {
        cudaFuncSetAttribute(hgemm_kernel,
            cudaFuncAttributeMaxDynamicSharedMemorySize, GEMM_SMEM);
        attr_done = 1;
    }

    void *p_xssm, *p_gh, *p_xh, *p_ygh, *p_wp1, *p_wp2, *p_wxh;
    cudaGetSymbolAddress(&p_xssm, g_xssm);
    cudaGetSymbolAddress(&p_gh,   g_gh);
    cudaGetSymbolAddress(&p_xh,   g_xh);
    cudaGetSymbolAddress(&p_ygh,  g_ygh);
    cudaGetSymbolAddress(&p_wp1,  g_wp1);
    cudaGetSymbolAddress(&p_wp2,  g_wp2);
    cudaGetSymbolAddress(&p_wxh,  g_wxh);

    // 1) prep
    prep_kernel<<<(PREP_TOTAL + 255) / 256, 256>>>(x, W_in, W_out, W_x, A_log,
                                                   out + Y_ELEMS);

    // 2) GEMM1 (fp16): -> (x_ssm fp32, silu(gate) fp16)
    {
        dim3 grid(2 * DD / GBN, MROWS / GBM);
        hgemm_kernel<<<grid, 256, GEMM_SMEM>>>(
            (const __half*)p_xh, (const uint32_t*)p_wp1, b_in,
            (float*)p_xssm, (__half*)p_gh, MROWS, 2 * DD, DD, 1);
    }

    // 3) depthwise causal conv + silu (fp32 in, fp16 out)
    conv_silu_kernel<<<Y_ELEMS/16/256, 256>>>(conv_w, conv_b);

    // 4) BC projection (fp16 tensor cores, 256 blocks)
    bc_mma_kernel<<<MROWS/32, 64>>>((const uint32_t*)p_wxh, b_x);

    // 5) chunked scan (SEG=128, TSEG=32)
    scan1_kernel<<<BB*SEG*4, 256>>>();
    combine_kernel<<<BB*NN*DD/256, 256>>>(out + Y_ELEMS);
    scan2_kernel<<<BB*SEG*4, 256>>>(D_par);

    // 6) GEMM2 (fp16): -> y (fp32 out)
    {
        dim3 grid(DD / GBN, MROWS / GBM);
        hgemm_kernel<<<grid, 256, GEMM_SMEM>>>(
            (const __half*)p_ygh, (const uint32_t*)p_wp2, b_out,
            out, nullptr, MROWS, DD, DD, 0);
    }
}

// round 16
// speedup vs baseline: 1.4731x; 1.4731x over previous
#include <cuda_runtime.h>
#include <cuda_fp16.h>
#include <math.h>
#include <stdint.h>

// ---------------- problem dims ----------------
#define BB 2
#define LL 4096
#define DD 1024
#define NN 16
#define KK 4
#define SEG 128
#define TSEG 32
#define MROWS (BB*LL)       // 8192
#define Y_ELEMS (BB*LL*DD)  // 8388608

// ---------------- scratch ----------------
__device__ float g_xssm[Y_ELEMS];
__device__ __align__(16) __half g_gh[Y_ELEMS];     // fp16 silu(gate)
__device__ __align__(16) __half g_xch[Y_ELEMS];    // fp16 x_conv
__device__ __align__(16) __half g_xh[Y_ELEMS];     // fp16 x
__device__ __align__(16) __half g_ygh[Y_ELEMS];    // fp16 y*silu(gate)
__device__ __align__(16) uint32_t g_wp1[(DD/2)*(2*DD)];  // W_in pair-packed
__device__ __align__(16) uint32_t g_wp2[(DD/2)*DD];      // W_out pair-packed
__device__ __align__(16) uint32_t g_wxh[(DD/2)*32];      // W_x pair-packed fp16
__device__ __align__(16) float g_adn[DD*NN];       // exp(-exp(A_log))
__device__ __align__(16) float g_adp[DD*NN];       // Adn^TSEG
__device__ float g_B[BB*LL*NN];
__device__ float g_C[BB*LL*NN];
__device__ float g_hseg[BB*SEG*NN*DD];
__device__ float g_h0[BB*SEG*NN*DD];

__device__ __forceinline__ uint32_t h2u(__half2 h) {
    union { __half2 h; uint32_t u; } cvt; cvt.h = h; return cvt.u;
}
__device__ __forceinline__ __half2 u2h(uint32_t u) {
    union { uint32_t u; __half2 h; } cvt; cvt.u = u; return cvt.h;
}

// ---------------- merged prep ----------------
#define X4    (Y_ELEMS/4)
#define WP1N  ((DD/2)*(2*DD))
#define WP2N  ((DD/2)*DD)
#define WXHN  ((DD/2)*32)
#define ADNN  (DD*NN)
#define PREP_TOTAL (X4 + WP1N + WP2N + WXHN + ADNN)

__global__ void prep_kernel(const float* __restrict__ x,
                            const float* __restrict__ W_in,
                            const float* __restrict__ W_out,
                            const float* __restrict__ W_x,
                            const float* __restrict__ A_log,
                            float* __restrict__ tail)
{
    int i = blockIdx.x * blockDim.x + threadIdx.x;
    if (blockIdx.x == 0 && threadIdx.x < BB * NN) tail[threadIdx.x] = 0.0f;
    if (i >= PREP_TOTAL) return;
    if (i < X4) {
        float4 v = ((const float4*)x)[i];
        uint2 o;
        o.x = h2u(__floats2half2_rn(v.x, v.y));
        o.y = h2u(__floats2half2_rn(v.z, v.w));
        ((uint2*)g_xh)[i] = o;
    } else if (i < X4 + WP1N) {
        int j = i - X4;
        int k2 = j >> 11, n = j & 2047;
        float lo = W_in[(size_t)(2 * k2) * 2048 + n];
        float hi = W_in[(size_t)(2 * k2 + 1) * 2048 + n];
        g_wp1[j] = h2u(__floats2half2_rn(lo, hi));
    } else if (i < X4 + WP1N + WP2N) {
        int j = i - X4 - WP1N;
        int k2 = j >> 10, n = j & 1023;
        float lo = W_out[(size_t)(2 * k2) * 1024 + n];
        float hi = W_out[(size_t)(2 * k2 + 1) * 1024 + n];
        g_wp2[j] = h2u(__floats2half2_rn(lo, hi));
    } else if (i < X4 + WP1N + WP2N + WXHN) {
        int j = i - X4 - WP1N - WP2N;
        int k2 = j >> 5, n = j & 31;
        float lo = W_x[(size_t)(2 * k2) * 32 + n];
        float hi = W_x[(size_t)(2 * k2 + 1) * 32 + n];
        g_wxh[j] = h2u(__floats2half2_rn(lo, hi));
    } else {
        int j = i - X4 - WP1N - WP2N - WXHN;
        float a = expf(-expf(A_log[j]));
        g_adn[j] = a;
        float p = a;
        #pragma unroll
        for (int q = 0; q < 5; q++) p = p * p;   // a^32 = a^TSEG
        g_adp[j] = p;
    }
}

// ======= fp16 mma.sync GEMM (m16n8k16): 128x128 block, 64x32 warp ======
#define GBM 128
#define GBN 128
#define GBK 32
#define AWSTRIDE 20
#define BWSTRIDE 136
#define A_STGW (GBM*AWSTRIDE)
#define B_STGW (16*BWSTRIDE)
#define STAGES 3
#define GEMM_SMEM (STAGES*(A_STGW+B_STGW)*4)   // 56832 bytes

__device__ __forceinline__ void cpasync16(void* dst, const void* src) {
    uint32_t s = (uint32_t)__cvta_generic_to_shared(dst);
    asm volatile("cp.async.cg.shared.global [%0], [%1], 16;\n" :: "r"(s), "l"(src));
}

__global__ __launch_bounds__(256)
void hgemm_kernel(const __half* __restrict__ A, const uint32_t* __restrict__ Bp,
                  const float* __restrict__ bias,
                  float* __restrict__ C0, __half* __restrict__ C1h,
                  int M, int N, int K, int mode)
{
    extern __shared__ uint32_t smw[];
    uint32_t* As_ = smw;
    uint32_t* Bs_ = smw + STAGES * A_STGW;

    const int tid  = threadIdx.x;
    const int lane = tid & 31;
    const int wid  = tid >> 5;
    const int wm   = wid >> 2;
    const int wn   = wid & 3;
    const int row_c = blockIdx.y * GBM;
    const int col_c = blockIdx.x * GBN;
    const int r  = lane >> 2;
    const int cq = lane & 3;

    float acc[4][4][4];
    #pragma unroll
    for (int i = 0; i < 4; i++)
        #pragma unroll
        for (int j = 0; j < 4; j++)
            #pragma unroll
            for (int v = 0; v < 4; v++) acc[i][j][v] = 0.0f;

    auto prefetch = [&](int k0, int st) {
        uint32_t* Asb = As_ + st * A_STGW;
        uint32_t* Bsb = Bs_ + st * B_STGW;
        #pragma unroll
        for (int s = 0; s < 2; s++) {
            int i2 = tid + s * 256;
            int arow = i2 >> 2, asub = i2 & 3;
            cpasync16(&Asb[arow * AWSTRIDE + asub * 4],
                      A + (size_t)(row_c + arow) * K + k0 + asub * 8);
            int brow = i2 >> 5, bsub = (i2 & 31) * 4;
            cpasync16(&Bsb[brow * BWSTRIDE + bsub],
                      Bp + (size_t)(k0 / 2 + brow) * N + col_c + bsub);
        }
        asm volatile("cp.async.commit_group;");
    };

    const int nchunks = K / GBK;   // 32
    prefetch(0, 0);
    prefetch(GBK, 1);

    for (int ch = 0; ch < nchunks; ch++) {
        if (ch >= nchunks - 2) asm volatile("cp.async.wait_group 0;");
        else                   asm volatile("cp.async.wait_group 1;");
        __syncthreads();
        if (ch + 2 < nchunks) prefetch((ch + 2) * GBK, (ch + 2) % STAGES);

        const uint32_t* Asb = As_ + (ch % STAGES) * A_STGW;
        const uint32_t* Bsb = Bs_ + (ch % STAGES) * B_STGW;

        #pragma unroll
        for (int ks = 0; ks < 2; ks++) {
            uint32_t af[4][4], bf[4][2];
            #pragma unroll
            for (int mi = 0; mi < 4; mi++) {
                int row = wm * 64 + mi * 16 + r;
                int w0  = ks * 8 + cq;
                af[mi][0] = Asb[row * AWSTRIDE + w0];
                af[mi][1] = Asb[(row + 8) * AWSTRIDE + w0];
                af[mi][2] = Asb[row * AWSTRIDE + w0 + 4];
                af[mi][3] = Asb[(row + 8) * AWSTRIDE + w0 + 4];
            }
            #pragma unroll
            for (int ni = 0; ni < 4; ni++) {
                int col = wn * 32 + ni * 8 + r;
                bf[ni][0] = Bsb[(ks * 8 + cq) * BWSTRIDE + col];
                bf[ni][1] = Bsb[(ks * 8 + cq + 4) * BWSTRIDE + col];
            }
            #pragma unroll
            for (int mi = 0; mi < 4; mi++)
                #pragma unroll
                for (int ni = 0; ni < 4; ni++) {
                    asm volatile(
                        "mma.sync.aligned.m16n8k16.row.col.f32.f16.f16.f32 "
                        "{%0,%1,%2,%3}, {%4,%5,%6,%7}, {%8,%9}, {%0,%1,%2,%3};"
                        : "+f"(acc[mi][ni][0]), "+f"(acc[mi][ni][1]),
                          "+f"(acc[mi][ni][2]), "+f"(acc[mi][ni][3])
                        : "r"(af[mi][0]), "r"(af[mi][1]),
                          "r"(af[mi][2]), "r"(af[mi][3]),
                          "r"(bf[ni][0]), "r"(bf[ni][1]));
                }
        }
        __syncthreads();
    }

    const int halfN = N >> 1;
    const bool gate_side = (mode == 1) && (col_c >= halfN);
    const int outw = (mode == 1) ? halfN : N;
    const int colsub = gate_side ? halfN : 0;

    #pragma unroll
    for (int mi = 0; mi < 4; mi++) {
        #pragma unroll
        for (int ni = 0; ni < 4; ni++) {
            int r0   = row_c + wm * 64 + mi * 16 + r;
            int colg = col_c + wn * 32 + ni * 8 + cq * 2;
            float b0 = bias[colg], b1 = bias[colg + 1];
            #pragma unroll
            for (int hv = 0; hv < 2; hv++) {
                int rr = r0 + hv * 8;
                float vx = acc[mi][ni][hv * 2 + 0] + b0;
                float vy = acc[mi][ni][hv * 2 + 1] + b1;
                if (gate_side) {
                    vx = vx / (1.0f + expf(-vx));
                    vy = vy / (1.0f + expf(-vy));
                    *(__half2*)(C1h + (size_t)rr * outw + colg - colsub) =
                        __floats2half2_rn(vx, vy);
                } else {
                    *(float2*)(C0 + (size_t)rr * outw + colg - colsub) =
                        make_float2(vx, vy);
                }
            }
        }
    }
}

// ------- depthwise causal conv (K=4) + SiLU, fp32 in / fp16 out --------
__global__ void conv_silu_kernel(const float* __restrict__ w,
                                 const float* __restrict__ cb)
{
    int idx = blockIdx.x * blockDim.x + threadIdx.x;
    if (idx >= Y_ELEMS / 16) return;
    int d0 = (idx & 255) * 4;
    int l0 = ((idx >> 8) & 1023) * 4;
    int b  = idx >> 18;
    const float* base = g_xssm + (size_t)b * LL * DD;

    float4 xv[7];
    #pragma unroll
    for (int j = 0; j < 7; j++) {
        int l = l0 - 3 + j;
        xv[j] = (l >= 0) ? *(const float4*)(base + (size_t)l * DD + d0)
                         : make_float4(0.f, 0.f, 0.f, 0.f);
    }
    float4 wr0 = *(const float4*)(w + (d0 + 0) * KK);
    float4 wr1 = *(const float4*)(w + (d0 + 1) * KK);
    float4 wr2 = *(const float4*)(w + (d0 + 2) * KK);
    float4 wr3 = *(const float4*)(w + (d0 + 3) * KK);
    float4 cbv = *(const float4*)(cb + d0);

    __half* outp = g_xch + (size_t)b * LL * DD;
    #pragma unroll
    for (int l = 0; l < 4; l++) {
        float4 v;
        v.x = cbv.x + wr0.x*xv[l].x + wr0.y*xv[l+1].x + wr0.z*xv[l+2].x + wr0.w*xv[l+3].x;
        v.y = cbv.y + wr1.x*xv[l].y + wr1.y*xv[l+1].y + wr1.z*xv[l+2].y + wr1.w*xv[l+3].y;
        v.z = cbv.z + wr2.x*xv[l].z + wr2.y*xv[l+1].z + wr2.z*xv[l+2].z + wr2.w*xv[l+3].z;
        v.w = cbv.w + wr3.x*xv[l].w + wr3.y*xv[l+1].w + wr3.z*xv[l+2].w + wr3.w*xv[l+3].w;
        v.x = v.x / (1.0f + expf(-v.x));
        v.y = v.y / (1.0f + expf(-v.y));
        v.z = v.z / (1.0f + expf(-v.z));
        v.w = v.w / (1.0f + expf(-v.w));
        uint2 o;
        o.x = h2u(__floats2half2_rn(v.x, v.y));
        o.y = h2u(__floats2half2_rn(v.z, v.w));
        *(uint2*)(outp + (size_t)(l0 + l) * DD + d0) = o;
    }
}

// ---------------- BC via fp16 tensor cores (128 thr, 64 rows) -----------
#define BCA_STR 20
#define BCW_STR 40

__global__ __launch_bounds__(128)
void bc_mma_kernel(const uint32_t* __restrict__ Wxh, const float* __restrict__ bx)
{
    __shared__ uint32_t As[3][64 * BCA_STR];
    __shared__ uint32_t Ws[3][16 * BCW_STR];

    const int tid  = threadIdx.x;
    const int lane = tid & 31;
    const int wid  = tid >> 5;
    const int r    = lane >> 2;
    const int cq   = lane & 3;
    const int r0   = blockIdx.x * 64;

    float acc[4][4];
    #pragma unroll
    for (int i = 0; i < 4; i++)
        #pragma unroll
        for (int v = 0; v < 4; v++) acc[i][v] = 0.0f;

    auto prefetch = [&](int ch, int st) {
        const int k0 = ch * 32;
        #pragma unroll
        for (int p = 0; p < 2; p++) {
            int i2 = tid + p * 128;
            int row = i2 >> 2, sub = i2 & 3;
            cpasync16(&As[st][row * BCA_STR + sub * 4],
                      g_xch + (size_t)(r0 + row) * DD + k0 + sub * 8);
        }
        {
            int row = tid >> 3, sub = tid & 7;
            cpasync16(&Ws[st][row * BCW_STR + sub * 4],
                      Wxh + (size_t)(k0 / 2 + row) * 32 + sub * 4);
        }
        asm volatile("cp.async.commit_group;");
    };

    const int nch = DD / 32;
    prefetch(0, 0);
    prefetch(1, 1);

    for (int ch = 0; ch < nch; ch++) {
        if (ch >= nch - 2) asm volatile("cp.async.wait_group 0;");
        else               asm volatile("cp.async.wait_group 1;");
        __syncthreads();
        if (ch + 2 < nch) prefetch(ch + 2, (ch + 2) % 3);

        const uint32_t* Asb = As[ch % 3];
        const uint32_t* Wsb = Ws[ch % 3];
        #pragma unroll
        for (int ks = 0; ks < 2; ks++) {
            uint32_t af[4], bf[4][2];
            int row = wid * 16 + r;
            int w0  = ks * 8 + cq;
            af[0] = Asb[row * BCA_STR + w0];
            af[1] = Asb[(row + 8) * BCA_STR + w0];
            af[2] = Asb[row * BCA_STR + w0 + 4];
            af[3] = Asb[(row + 8) * BCA_STR + w0 + 4];
            #pragma unroll
            for (int ni = 0; ni < 4; ni++) {
                bf[ni][0] = Wsb[(ks * 8 + cq) * BCW_STR + ni * 8 + r];
                bf[ni][1] = Wsb[(ks * 8 + cq + 4) * BCW_STR + ni * 8 + r];
            }
            #pragma unroll
            for (int ni = 0; ni < 4; ni++) {
                asm volatile(
                    "mma.sync.aligned.m16n8k16.row.col.f32.f16.f16.f32 "
                    "{%0,%1,%2,%3}, {%4,%5,%6,%7}, {%8,%9}, {%0,%1,%2,%3};"
                    : "+f"(acc[ni][0]), "+f"(acc[ni][1]),
                      "+f"(acc[ni][2]), "+f"(acc[ni][3])
                    : "r"(af[0]), "r"(af[1]), "r"(af[2]), "r"(af[3]),
                      "r"(bf[ni][0]), "r"(bf[ni][1]));
            }
        }
        __syncthreads();
    }

    #pragma unroll
    for (int ni = 0; ni < 4; ni++) {
        #pragma unroll
        for (int v = 0; v < 4; v++) {
            int row = r0 + wid * 16 + r + (v >> 1) * 8;
            int col = ni * 8 + cq * 2 + (v & 1);
            float val = acc[ni][v] + bx[col];
            if (col < NN) g_B[row * NN + col] = val;
            else          g_C[row * NN + (col - NN)] = val;
        }
    }
}

// ---------------- scan pass 1 (TSEG=32, one chunk) ----------------
__global__ __launch_bounds__(256)
void scan1_kernel()
{
    __shared__ float Xsm[32][256];
    __shared__ __align__(16) float Bsm[32][16];

    const int tid = threadIdx.x;
    const int dt  = blockIdx.x & 3;
    const int s   = (blockIdx.x >> 2) & (SEG - 1);
    const int b   = blockIdx.x >> 9;
    const int d   = dt * 256 + tid;
    const int t0  = s * TSEG;

    float Adn[16];
    #pragma unroll
    for (int q = 0; q < 4; q++)
        *(float4*)&Adn[q * 4] = *(const float4*)&g_adn[d * NN + q * 4];

    float h[16];
    #pragma unroll
    for (int n = 0; n < 16; n++) h[n] = 0.0f;

    const float* Bp = g_B + (size_t)b * LL * NN;
    if (tid < 128)
        ((float4*)Bsm)[tid] = ((const float4*)(Bp + (size_t)t0 * NN))[tid];
    {
        const uint32_t* xu = (const uint32_t*)(g_xch + (size_t)b * LL * DD + dt * 256);
        #pragma unroll
        for (int p = 0; p < 16; p++) {
            int j = tid + p * 256;
            int row = j >> 7, c = j & 127;
            float2 f = __half22float2(u2h(xu[(size_t)(t0 + row) * (DD / 2) + c]));
            Xsm[row][c * 2]     = f.x;
            Xsm[row][c * 2 + 1] = f.y;
        }
    }
    __syncthreads();

    #pragma unroll 4
    for (int tl = 0; tl < 32; tl++) {
        float xc = Xsm[tl][tid];
        float4 b0 = *(const float4*)&Bsm[tl][0];
        float4 b1 = *(const float4*)&Bsm[tl][4];
        float4 b2 = *(const float4*)&Bsm[tl][8];
        float4 b3 = *(const float4*)&Bsm[tl][12];
        h[0]  = fmaf(Adn[0],  h[0],  xc * b0.x);
        h[1]  = fmaf(Adn[1],  h[1],  xc * b0.y);
        h[2]  = fmaf(Adn[2],  h[2],  xc * b0.z);
        h[3]  = fmaf(Adn[3],  h[3],  xc * b0.w);
        h[4]  = fmaf(Adn[4],  h[4],  xc * b1.x);
        h[5]  = fmaf(Adn[5],  h[5],  xc * b1.y);
        h[6]  = fmaf(Adn[6],  h[6],  xc * b1.z);
        h[7]  = fmaf(Adn[7],  h[7],  xc * b1.w);
        h[8]  = fmaf(Adn[8],  h[8],  xc * b2.x);
        h[9]  = fmaf(Adn[9],  h[9],  xc * b2.y);
        h[10] = fmaf(Adn[10], h[10], xc * b2.z);
        h[11] = fmaf(Adn[11], h[11], xc * b2.w);
        h[12] = fmaf(Adn[12], h[12], xc * b3.x);
        h[13] = fmaf(Adn[13], h[13], xc * b3.y);
        h[14] = fmaf(Adn[14], h[14], xc * b3.z);
        h[15] = fmaf(Adn[15], h[15], xc * b3.w);
    }
    #pragma unroll
    for (int n = 0; n < 16; n++)
        g_hseg[((size_t)(b * SEG + s) * NN + n) * DD + d] = h[n];
}

// ---------------- combine ----------------
__global__ __launch_bounds__(256)
void combine_kernel(float* __restrict__ fstate)
{
    int idx = blockIdx.x * 256 + threadIdx.x;
    int d = idx & (DD - 1);
    int bn = idx >> 10;
    int n = bn & 15;
    int b = bn >> 4;

    float p = g_adp[d * NN + n];

    size_t base = ((size_t)(b * SEG) * NN + n) * DD + d;
    const size_t stride = (size_t)NN * DD;
    float h = 0.0f;
    #pragma unroll 4
    for (int s = 0; s < SEG; s++) {
        g_h0[base + s * stride] = h;
        h = fmaf(p, h, g_hseg[base + s * stride]);
    }
    #pragma unroll
    for (int off = 16; off >= 1; off >>= 1)
        h += __shfl_xor_sync(0xffffffffu, h, off);
    if ((threadIdx.x & 31) == 0)
        atomicAdd(&fstate[b * NN + n], h * (1.0f / (float)DD));
}

// ---------------- scan pass 2 (TSEG=32, one chunk) ----------------
__global__ __launch_bounds__(256)
void scan2_kernel(const float* __restrict__ Dp)
{
    __shared__ float Xsm[32][256];
    __shared__ __align__(16) float Bsm[32][16];
    __shared__ __align__(16) float Csm[32][16];

    const int tid = threadIdx.x;
    const int dt  = blockIdx.x & 3;
    const int s   = (blockIdx.x >> 2) & (SEG - 1);
    const int b   = blockIdx.x >> 9;
    const int d   = dt * 256 + tid;
    const int t0  = s * TSEG;

    float Adn[16];
    #pragma unroll
    for (int q = 0; q < 4; q++)
        *(float4*)&Adn[q * 4] = *(const float4*)&g_adn[d * NN + q * 4];
    const float Dd = Dp[d];

    float h[16];
    {
        size_t base = ((size_t)(b * SEG + s) * NN) * DD + d;
        #pragma unroll
        for (int n = 0; n < 16; n++) h[n] = g_h0[base + (size_t)n * DD];
    }

    const float* Bp = g_B + (size_t)b * LL * NN;
    const float* Cp = g_C + (size_t)b * LL * NN;
    if (tid < 128) {
        ((float4*)Bsm)[tid] = ((const float4*)(Bp + (size_t)t0 * NN))[tid];
        ((float4*)Csm)[tid] = ((const float4*)(Cp + (size_t)t0 * NN))[tid];
    }
    {
        const uint32_t* xu = (const uint32_t*)(g_xch + (size_t)b * LL * DD + dt * 256);
        #pragma unroll
        for (int p = 0; p < 16; p++) {
            int j = tid + p * 256;
            int row = j >> 7, c = j & 127;
            float2 f = __half22float2(u2h(xu[(size_t)(t0 + row) * (DD / 2) + c]));
            Xsm[row][c * 2]     = f.x;
            Xsm[row][c * 2 + 1] = f.y;
        }
    }
    __syncthreads();

    const __half* gp = g_gh  + (size_t)b * LL * DD + dt * 256;
    __half*      yp  = g_ygh + (size_t)b * LL * DD + dt * 256;

    #pragma unroll 2
    for (int tl = 0; tl < 32; tl++) {
        float xc = Xsm[tl][tid];
        float4 b0 = *(const float4*)&Bsm[tl][0];
        float4 b1 = *(const float4*)&Bsm[tl][4];
        float4 b2 = *(const float4*)&Bsm[tl][8];
        float4 b3 = *(const float4*)&Bsm[tl][12];
        h[0]  = fmaf(Adn[0],  h[0],  xc * b0.x);
        h[1]  = fmaf(Adn[1],  h[1],  xc * b0.y);
        h[2]  = fmaf(Adn[2],  h[2],  xc * b0.z);
        h[3]  = fmaf(Adn[3],  h[3],  xc * b0.w);
        h[4]  = fmaf(Adn[4],  h[4],  xc * b1.x);
        h[5]  = fmaf(Adn[5],  h[5],  xc * b1.y);
        h[6]  = fmaf(Adn[6],  h[6],  xc * b1.z);
        h[7]  = fmaf(Adn[7],  h[7],  xc * b1.w);
        h[8]  = fmaf(Adn[8],  h[8],  xc * b2.x);
        h[9]  = fmaf(Adn[9],  h[9],  xc * b2.y);
        h[10] = fmaf(Adn[10], h[10], xc * b2.z);
        h[11] = fmaf(Adn[11], h[11], xc * b2.w);
        h[12] = fmaf(Adn[12], h[12], xc * b3.x);
        h[13] = fmaf(Adn[13], h[13], xc * b3.y);
        h[14] = fmaf(Adn[14], h[14], xc * b3.z);
        h[15] = fmaf(Adn[15], h[15], xc * b3.w);
        float4 c0 = *(const float4*)&Csm[tl][0];
        float4 c1 = *(const float4*)&Csm[tl][4];
        float4 c2 = *(const float4*)&Csm[tl][8];
        float4 c3 = *(const float4*)&Csm[tl][12];
        float y0 = fmaf(c0.x, h[0],  fmaf(c0.y, h[1],
                   fmaf(c0.z, h[2],  c0.w * h[3])));
        float y1 = fmaf(c1.x, h[4],  fmaf(c1.y, h[5],
                   fmaf(c1.z, h[6],  c1.w * h[7])));
        float y2 = fmaf(c2.x, h[8],  fmaf(c2.y, h[9],
                   fmaf(c2.z, h[10], c2.w * h[11])));
        float y3 = fmaf(c3.x, h[12], fmaf(c3.y, h[13],
                   fmaf(c3.z, h[14], c3.w * h[15])));
        float y = ((y0 + y1) + (y2 + y3)) + Dd * xc;
        float gv = __half2float(gp[(size_t)(t0 + tl) * DD + tid]);
        yp[(size_t)(t0 + tl) * DD + tid] = __float2half_rn(y * gv);
    }
}

// ---------------- launcher ----------------
extern "C" void kernel_launch(void* const* d_in, const int* in_sizes, int n_in,
                              void* d_out, int out_size)
{
    const float* x      = (const float*)d_in[0];
    const float* W_in   = (const float*)d_in[1];
    const float* b_in   = (const float*)d_in[2];
    const float* conv_w = (const float*)d_in[3];
    const float* conv_b = (const float*)d_in[4];
    const float* W_x    = (const float*)d_in[5];
    const float* b_x    = (const float*)d_in[6];
    const float* A_log  = (const float*)d_in[7];
    const float* D_par  = (const float*)d_in[8];
    const float* W_out  = (const float*)d_in[9];
    const float* b_out  = (const float*)d_in[10];
    float* out = (float*)d_out;

    static int attr_done = 0;
    if (!attr_done) {
        cudaFuncSetAttribute(hgemm_kernel,
            cudaFuncAttributeMaxDynamicSharedMemorySize, GEMM_SMEM);
        attr_done = 1;
    }

    void *p_xssm, *p_gh, *p_xh, *p_ygh, *p_wp1, *p_wp2, *p_wxh;
    cudaGetSymbolAddress(&p_xssm, g_xssm);
    cudaGetSymbolAddress(&p_gh,   g_gh);
    cudaGetSymbolAddress(&p_xh,   g_xh);
    cudaGetSymbolAddress(&p_ygh,  g_ygh);
    cudaGetSymbolAddress(&p_wp1,  g_wp1);
    cudaGetSymbolAddress(&p_wp2,  g_wp2);
    cudaGetSymbolAddress(&p_wxh,  g_wxh);

    // 1) prep
    prep_kernel<<<(PREP_TOTAL + 255) / 256, 256>>>(x, W_in, W_out, W_x, A_log,
                                                   out + Y_ELEMS);

    // 2) GEMM1 (fp16): -> (x_ssm fp32, silu(gate) fp16)
    {
        dim3 grid(2 * DD / GBN, MROWS / GBM);
        hgemm_kernel<<<grid, 256, GEMM_SMEM>>>(
            (const __half*)p_xh, (const uint32_t*)p_wp1, b_in,
            (float*)p_xssm, (__half*)p_gh, MROWS, 2 * DD, DD, 1);
    }

    // 3) depthwise causal conv + silu (fp32 in, fp16 out)
    conv_silu_kernel<<<Y_ELEMS/16/256, 256>>>(conv_w, conv_b);

    // 4) BC projection (fp16 tensor cores)
    bc_mma_kernel<<<MROWS/64, 128>>>((const uint32_t*)p_wxh, b_x);

    // 5) chunked scan (SEG=128, TSEG=32)
    scan1_kernel<<<BB*SEG*4, 256>>>();
    combine_kernel<<<BB*NN*DD/256, 256>>>(out + Y_ELEMS);
    scan2_kernel<<<BB*SEG*4, 256>>>(D_par);

    // 6) GEMM2 (fp16): -> y (fp32 out)
    {
        dim3 grid(DD / GBN, MROWS / GBM);
        hgemm_kernel<<<grid, 256, GEMM_SMEM>>>(
            (const __half*)p_ygh, (const uint32_t*)p_wp2, b_out,
            out, nullptr, MROWS, DD, DD, 0);
    }
}